// round 1
// baseline (speedup 1.0000x reference)
#include <cuda_runtime.h>

#define BB   2
#define HH   12
#define NN   2048
#define CC   768
#define DD   64
#define BHND (BB*HH*NN*DD)

// Scratch (no allocations allowed)
__device__ float g_q[BHND];
__device__ float g_k[BHND];
__device__ float g_v[BHND];
__device__ float g_att[BB*NN*CC];

// ---------------------------------------------------------------------------
// QKV GEMM: C[m, n] = sum_k X[m,k] * W[n,k];  M=4096, N=2304, K=768
// Scatter into g_q/g_k/g_v laid out [B,H,N,D].
// ---------------------------------------------------------------------------
__global__ __launch_bounds__(256) void qkv_gemm(const float* __restrict__ X,
                                                const float* __restrict__ W)
{
    __shared__ float As[64][17];
    __shared__ float Bs[64][17];
    const int tid = threadIdx.x;
    const int tx = tid & 15, ty = tid >> 4;
    const int m0 = blockIdx.y * 64, n0 = blockIdx.x * 64;

    const int e  = tid * 4;
    const int lr = e >> 4, lc = e & 15;

    float acc[4][4] = {};

    for (int k0 = 0; k0 < CC; k0 += 16) {
        float4 a4 = *(const float4*)(X + (size_t)(m0 + lr) * CC + k0 + lc);
        float4 b4 = *(const float4*)(W + (size_t)(n0 + lr) * CC + k0 + lc);
        As[lr][lc] = a4.x; As[lr][lc+1] = a4.y; As[lr][lc+2] = a4.z; As[lr][lc+3] = a4.w;
        Bs[lr][lc] = b4.x; Bs[lr][lc+1] = b4.y; Bs[lr][lc+2] = b4.z; Bs[lr][lc+3] = b4.w;
        __syncthreads();
        #pragma unroll
        for (int kk = 0; kk < 16; kk++) {
            float a[4], b[4];
            #pragma unroll
            for (int i = 0; i < 4; i++) a[i] = As[ty + 16*i][kk];
            #pragma unroll
            for (int j = 0; j < 4; j++) b[j] = Bs[tx + 16*j][kk];
            #pragma unroll
            for (int i = 0; i < 4; i++)
                #pragma unroll
                for (int j = 0; j < 4; j++)
                    acc[i][j] += a[i] * b[j];
        }
        __syncthreads();
    }

    #pragma unroll
    for (int i = 0; i < 4; i++) {
        const int m  = m0 + ty + 16*i;
        const int bb = m >> 11;        // m / 2048
        const int nn = m & 2047;
        #pragma unroll
        for (int j = 0; j < 4; j++) {
            const int n     = n0 + tx + 16*j;
            const int which = n / CC;
            const int rem   = n - which * CC;
            const int h     = rem >> 6;
            const int d     = rem & 63;
            float* dst = (which == 0) ? g_q : (which == 1) ? g_k : g_v;
            dst[(((size_t)bb * HH + h) * NN + nn) * DD + d] = acc[i][j];
        }
    }
}

// ---------------------------------------------------------------------------
// Flash attention: one block per (b, h, 64-query tile). Online softmax.
// smem pitch 68 floats to dodge bank conflicts. P written via smem.
// ---------------------------------------------------------------------------
#define LDP 68

__global__ __launch_bounds__(256) void attn_kernel(const float* __restrict__ mask)
{
    extern __shared__ float sm[];
    float* Qs = sm;                 // 64 * 68
    float* Ks = Qs + 64 * LDP;
    float* Vs = Ks + 64 * LDP;
    float* Ps = Vs + 64 * LDP;
    float* mb = Ps + 64 * LDP;      // 64

    const int tid = threadIdx.x;
    const int tx  = tid & 15, ty = tid >> 4;
    const int q0  = blockIdx.x * 64;
    const int h   = blockIdx.y;
    const int b   = blockIdx.z;
    const size_t base = ((size_t)(b * HH + h)) * NN * DD;
    const float scale = 0.125f;     // 1/sqrt(64)

    // Load Q tile (coalesced float4; visibility guaranteed by first loop sync)
    for (int ee = tid * 4; ee < 64 * 64; ee += 1024) {
        const int r = ee >> 6, c = ee & 63;
        *(float4*)(Qs + r * LDP + c) =
            *(const float4*)(g_q + base + (size_t)(q0 + r) * DD + c);
    }

    float m_i[4], l_i[4], o[4][4];
    #pragma unroll
    for (int i = 0; i < 4; i++) {
        m_i[i] = -1e30f; l_i[i] = 0.f;
        #pragma unroll
        for (int j = 0; j < 4; j++) o[i][j] = 0.f;
    }

    for (int kt = 0; kt < NN; kt += 64) {
        __syncthreads();   // prior-tile consumers done (and Q-load visible on iter 0)
        for (int ee = tid * 4; ee < 64 * 64; ee += 1024) {
            const int r = ee >> 6, c = ee & 63;
            *(float4*)(Ks + r * LDP + c) =
                *(const float4*)(g_k + base + (size_t)(kt + r) * DD + c);
            *(float4*)(Vs + r * LDP + c) =
                *(const float4*)(g_v + base + (size_t)(kt + r) * DD + c);
        }
        if (tid < 64) mb[tid] = mask[b * NN + kt + tid] * (-1000.0f);
        __syncthreads();

        // Phase A: S = Q @ K^T  (rows ty*4+i, cols tx+16*j)
        float s[4][4] = {};
        #pragma unroll
        for (int d4 = 0; d4 < 16; d4++) {
            float4 q4[4], k4[4];
            #pragma unroll
            for (int i = 0; i < 4; i++)
                q4[i] = *(const float4*)(Qs + (ty * 4 + i) * LDP + d4 * 4);
            #pragma unroll
            for (int j = 0; j < 4; j++)
                k4[j] = *(const float4*)(Ks + (tx + 16 * j) * LDP + d4 * 4);
            #pragma unroll
            for (int i = 0; i < 4; i++)
                #pragma unroll
                for (int j = 0; j < 4; j++)
                    s[i][j] += q4[i].x * k4[j].x + q4[i].y * k4[j].y
                             + q4[i].z * k4[j].z + q4[i].w * k4[j].w;
        }

        // Online softmax per row (16 tx lanes share a row; xor-shuffle reduce)
        #pragma unroll
        for (int i = 0; i < 4; i++) {
            float mloc = -1e30f;
            #pragma unroll
            for (int j = 0; j < 4; j++) {
                s[i][j] = s[i][j] * scale + mb[tx + 16 * j];
                mloc = fmaxf(mloc, s[i][j]);
            }
            #pragma unroll
            for (int off = 1; off < 16; off <<= 1)
                mloc = fmaxf(mloc, __shfl_xor_sync(0xffffffffu, mloc, off));
            const float mnew  = fmaxf(m_i[i], mloc);
            const float alpha = __expf(m_i[i] - mnew);
            float lloc = 0.f;
            #pragma unroll
            for (int j = 0; j < 4; j++) {
                const float p = __expf(s[i][j] - mnew);
                s[i][j] = p;
                lloc += p;
            }
            #pragma unroll
            for (int off = 1; off < 16; off <<= 1)
                lloc += __shfl_xor_sync(0xffffffffu, lloc, off);
            l_i[i] = l_i[i] * alpha + lloc;
            m_i[i] = mnew;
            #pragma unroll
            for (int j = 0; j < 4; j++) {
                o[i][j] *= alpha;
                Ps[(ty * 4 + i) * LDP + tx + 16 * j] = s[i][j];
            }
        }
        __syncthreads();

        // Phase B: O += P @ V  (d-cols tx+16*j)
        #pragma unroll 8
        for (int jj = 0; jj < 64; jj++) {
            float p_[4], v_[4];
            #pragma unroll
            for (int i = 0; i < 4; i++) p_[i] = Ps[(ty * 4 + i) * LDP + jj];
            #pragma unroll
            for (int j = 0; j < 4; j++) v_[j] = Vs[jj * LDP + tx + 16 * j];
            #pragma unroll
            for (int i = 0; i < 4; i++)
                #pragma unroll
                for (int j = 0; j < 4; j++)
                    o[i][j] += p_[i] * v_[j];
        }
    }

    // Write [B, N, C] with C index = h*64 + d
    #pragma unroll
    for (int i = 0; i < 4; i++) {
        const float inv = 1.0f / l_i[i];
        const int r = q0 + ty * 4 + i;
        #pragma unroll
        for (int j = 0; j < 4; j++) {
            const int d = tx + 16 * j;
            g_att[((size_t)(b * NN + r)) * CC + h * 64 + d] = o[i][j] * inv;
        }
    }
}

// ---------------------------------------------------------------------------
// Projection GEMM: out[m, n] = sum_k att[m,k] * Wp[n,k] + bias[n]
// M=4096, N=768, K=768
// ---------------------------------------------------------------------------
__global__ __launch_bounds__(256) void proj_gemm(const float* __restrict__ Wp,
                                                 const float* __restrict__ bias,
                                                 float* __restrict__ out)
{
    __shared__ float As[64][17];
    __shared__ float Bs[64][17];
    const int tid = threadIdx.x;
    const int tx = tid & 15, ty = tid >> 4;
    const int m0 = blockIdx.y * 64, n0 = blockIdx.x * 64;

    const int e  = tid * 4;
    const int lr = e >> 4, lc = e & 15;

    float acc[4][4] = {};

    for (int k0 = 0; k0 < CC; k0 += 16) {
        float4 a4 = *(const float4*)(g_att + (size_t)(m0 + lr) * CC + k0 + lc);
        float4 b4 = *(const float4*)(Wp    + (size_t)(n0 + lr) * CC + k0 + lc);
        As[lr][lc] = a4.x; As[lr][lc+1] = a4.y; As[lr][lc+2] = a4.z; As[lr][lc+3] = a4.w;
        Bs[lr][lc] = b4.x; Bs[lr][lc+1] = b4.y; Bs[lr][lc+2] = b4.z; Bs[lr][lc+3] = b4.w;
        __syncthreads();
        #pragma unroll
        for (int kk = 0; kk < 16; kk++) {
            float a[4], b[4];
            #pragma unroll
            for (int i = 0; i < 4; i++) a[i] = As[ty + 16*i][kk];
            #pragma unroll
            for (int j = 0; j < 4; j++) b[j] = Bs[tx + 16*j][kk];
            #pragma unroll
            for (int i = 0; i < 4; i++)
                #pragma unroll
                for (int j = 0; j < 4; j++)
                    acc[i][j] += a[i] * b[j];
        }
        __syncthreads();
    }

    #pragma unroll
    for (int i = 0; i < 4; i++) {
        const int m = m0 + ty + 16*i;
        #pragma unroll
        for (int j = 0; j < 4; j++) {
            const int n = n0 + tx + 16*j;
            out[(size_t)m * CC + n] = acc[i][j] + bias[n];
        }
    }
}

// ---------------------------------------------------------------------------

extern "C" void kernel_launch(void* const* d_in, const int* in_sizes, int n_in,
                              void* d_out, int out_size)
{
    const float* x      = (const float*)d_in[0];
    const float* mask   = (const float*)d_in[1];
    const float* qkv_w  = (const float*)d_in[2];
    const float* proj_w = (const float*)d_in[3];
    const float* proj_b = (const float*)d_in[4];
    float* out = (float*)d_out;

    const int smem_attn = (4 * 64 * LDP + 64) * (int)sizeof(float); // 69,888 B
    cudaFuncSetAttribute(attn_kernel,
                         cudaFuncAttributeMaxDynamicSharedMemorySize, smem_attn);

    // 1) QKV projection
    qkv_gemm<<<dim3(3 * CC / 64, (BB * NN) / 64), 256>>>(x, qkv_w);
    // 2) Fused masked flash attention
    attn_kernel<<<dim3(NN / 64, HH, BB), 256, smem_attn>>>(mask);
    // 3) Output projection + bias
    proj_gemm<<<dim3(CC / 64, (BB * NN) / 64), 256>>>(proj_w, proj_b, out);
}

// round 2
// speedup vs baseline: 1.9188x; 1.9188x over previous
#include <cuda_runtime.h>

#define BB   2
#define HH   12
#define NN   2048
#define CC   768
#define DD   64
#define NT   (CC/8)

// Scratch (no allocations allowed)
__device__ float g_q[BB*HH*NN*DD];
__device__ float g_k[BB*HH*NN*DD];
__device__ float g_v[BB*HH*NN*DD];
__device__ float g_att[BB*NN*CC];
__device__ int   g_idx[BB*NN];
__device__ int   g_cnt[BB];

// ---------------------------------------------------------------------------
// Compaction: per batch, gather indices of visible keys (mask == 0).
// Masked keys get -1000 bias -> exp underflows to exactly 0 in fp32, so
// dropping them is EXACT vs the fp32 reference.
// ---------------------------------------------------------------------------
__global__ __launch_bounds__(1024) void compact_kernel(const float* __restrict__ mask)
{
    __shared__ int wsum[32];
    const int b = blockIdx.x;
    const int t = threadIdx.x;            // 0..1023, each handles 2 positions
    const int p0 = 2 * t, p1 = 2 * t + 1;
    const int v0 = (mask[b * NN + p0] == 0.0f) ? 1 : 0;
    const int v1 = (mask[b * NN + p1] == 0.0f) ? 1 : 0;
    const int s  = v0 + v1;

    int sc = s;                            // inclusive warp scan
    #pragma unroll
    for (int o = 1; o < 32; o <<= 1) {
        int n = __shfl_up_sync(0xffffffffu, sc, o);
        if ((t & 31) >= o) sc += n;
    }
    if ((t & 31) == 31) wsum[t >> 5] = sc;
    __syncthreads();
    if (t < 32) {
        int w = wsum[t];
        #pragma unroll
        for (int o = 1; o < 32; o <<= 1) {
            int n = __shfl_up_sync(0xffffffffu, w, o);
            if (t >= o) w += n;
        }
        wsum[t] = w;                       // inclusive scan of warp sums
    }
    __syncthreads();
    const int excl = (sc - s) + ((t >= 32) ? wsum[(t >> 5) - 1] : 0);
    if (v0) g_idx[b * NN + excl] = p0;
    if (v1) g_idx[b * NN + excl + v0] = p1;
    if (t == 1023) g_cnt[b] = excl + s;
}

// ---------------------------------------------------------------------------
// 128x64 GEMM tile, K-step 8, double-buffered smem, 8x4 per thread.
// C[m,n] = sum_k A[m,k] * W[n,k]   (both K-contiguous row-major)
// MODE 0: Q projection  (A = x flat [4096,768], W = qkv_w rows 0..767)
//         -> g_q [B,H,N,D]
// MODE 1: K/V projection over COMPACTED rows (A = x gathered via g_idx,
//         W = qkv_w + 768*CC, N-dim 1536) -> g_k/g_v at compacted positions
// MODE 2: output projection (A = g_att, W = proj_w, +bias) -> out
// ---------------------------------------------------------------------------
template<int MODE>
__global__ __launch_bounds__(256) void gemm_k(const float* __restrict__ A,
                                              const float* __restrict__ W,
                                              const float* __restrict__ bias,
                                              float* __restrict__ out)
{
    __shared__ __align__(16) float As[2][8][132];
    __shared__ __align__(16) float Bs[2][8][68];

    const int tid = threadIdx.x;
    const int n0 = blockIdx.x * 64;
    const int m0 = blockIdx.y * 128;
    int b = 0, cnt = 0;
    if (MODE == 1) {
        b = blockIdx.z;
        cnt = g_cnt[b];
        if (m0 >= cnt) return;
    }

    const float* Ap = (MODE == 2) ? g_att : A;

    // ---- global load addressing ----
    const int lr = tid >> 1;               // 0..127  (A row within tile)
    const int lk = (tid & 1) * 4;          // 0 or 4  (k sub-offset)
    size_t a_off;
    if (MODE == 1) {
        const int mrow = m0 + lr;
        const int src  = (mrow < cnt) ? g_idx[b * NN + mrow] : 0;
        a_off = ((size_t)(b * NN + src)) * CC + lk;
    } else {
        a_off = (size_t)(m0 + lr) * CC + lk;
    }
    size_t b_off = 0;
    if (tid < 128) b_off = (size_t)(n0 + (tid >> 1)) * CC + lk;

    // ---- compute decomposition: warps 4(y) x 2(x); lane 4(y) x 8(x) ----
    const int w = tid >> 5, lane = tid & 31;
    const int wy = w >> 1, wx = w & 1;
    const int ly = lane >> 3, lx = lane & 7;
    const int row0 = wy * 32 + ly * 4;     // rows row0..+3 and row0+16..+19
    const int col0 = wx * 32 + lx * 4;     // cols col0..+3

    float acc[8][4] = {};

    float4 af = *(const float4*)(Ap + a_off);
    float4 bf = make_float4(0.f, 0.f, 0.f, 0.f);
    if (tid < 128) bf = *(const float4*)(W + b_off);

    int buf = 0;
    for (int kt = 0; kt < NT; kt++) {
        As[buf][lk + 0][lr] = af.x;
        As[buf][lk + 1][lr] = af.y;
        As[buf][lk + 2][lr] = af.z;
        As[buf][lk + 3][lr] = af.w;
        if (tid < 128) {
            const int br = tid >> 1;
            Bs[buf][lk + 0][br] = bf.x;
            Bs[buf][lk + 1][br] = bf.y;
            Bs[buf][lk + 2][br] = bf.z;
            Bs[buf][lk + 3][br] = bf.w;
        }
        __syncthreads();
        if (kt + 1 < NT) {
            af = *(const float4*)(Ap + a_off + (kt + 1) * 8);
            if (tid < 128) bf = *(const float4*)(W + b_off + (kt + 1) * 8);
        }
        #pragma unroll
        for (int kc = 0; kc < 8; kc++) {
            float4 a0 = *(const float4*)&As[buf][kc][row0];
            float4 a1 = *(const float4*)&As[buf][kc][row0 + 16];
            float4 b4 = *(const float4*)&Bs[buf][kc][col0];
            const float av[8] = {a0.x, a0.y, a0.z, a0.w, a1.x, a1.y, a1.z, a1.w};
            const float bv[4] = {b4.x, b4.y, b4.z, b4.w};
            #pragma unroll
            for (int i = 0; i < 8; i++)
                #pragma unroll
                for (int j = 0; j < 4; j++)
                    acc[i][j] += av[i] * bv[j];
        }
        buf ^= 1;
    }

    // ---- epilogue ----
    #pragma unroll
    for (int i = 0; i < 8; i++) {
        const int rloc = row0 + ((i < 4) ? i : (i + 12));  // +16 for upper half
        const int m = m0 + rloc;
        if (MODE == 1 && m >= cnt) continue;
        #pragma unroll
        for (int j = 0; j < 4; j++) {
            const int c = n0 + col0 + j;
            const float v = acc[i][j];
            if (MODE == 0) {
                const int bpos = m >> 11, nn = m & 2047;
                const int h = c >> 6, d = c & 63;
                g_q[(((size_t)bpos * HH + h) * NN + nn) * DD + d] = v;
            } else if (MODE == 1) {
                const bool isv = (c >= 768);
                const int cc2 = isv ? (c - 768) : c;
                const int h = cc2 >> 6, d = cc2 & 63;
                float* dst = isv ? g_v : g_k;
                dst[(((size_t)b * HH + h) * NN + m) * DD + d] = v;
            } else {
                out[(size_t)m * CC + c] = v + bias[c];
            }
        }
    }
}

// ---------------------------------------------------------------------------
// Flash attention over COMPACTED keys. One block per (b, h, 64-query tile).
// Online softmax; smem pitch 68 floats. No mask bias (all keys visible);
// only the final partial tile needs -inf guards.
// ---------------------------------------------------------------------------
#define LDP 68

__global__ __launch_bounds__(256) void attn_kernel()
{
    extern __shared__ float sm[];
    float* Qs = sm;                 // 64 * 68
    float* Ks = Qs + 64 * LDP;
    float* Vs = Ks + 64 * LDP;
    float* Ps = Vs + 64 * LDP;
    float* mb = Ps + 64 * LDP;      // 64 tail-guard biases

    const int tid = threadIdx.x;
    const int tx  = tid & 15, ty = tid >> 4;
    const int q0  = blockIdx.x * 64;
    const int h   = blockIdx.y;
    const int b   = blockIdx.z;
    const int cnt = g_cnt[b];
    const size_t base = ((size_t)(b * HH + h)) * NN * DD;
    const float scale = 0.125f;     // 1/sqrt(64)

    for (int ee = tid * 4; ee < 64 * 64; ee += 1024) {
        const int r = ee >> 6, c = ee & 63;
        *(float4*)(Qs + r * LDP + c) =
            *(const float4*)(g_q + base + (size_t)(q0 + r) * DD + c);
    }

    float m_i[4], l_i[4], o[4][4];
    #pragma unroll
    for (int i = 0; i < 4; i++) {
        m_i[i] = -1e30f; l_i[i] = 0.f;
        #pragma unroll
        for (int j = 0; j < 4; j++) o[i][j] = 0.f;
    }

    const float4 z4 = make_float4(0.f, 0.f, 0.f, 0.f);

    for (int kt = 0; kt < cnt; kt += 64) {
        __syncthreads();   // prior-tile consumers done (and Q-load visible on iter 0)
        for (int ee = tid * 4; ee < 64 * 64; ee += 1024) {
            const int r = ee >> 6, c = ee & 63;
            const int gr = kt + r;
            float4 k4 = z4, v4 = z4;
            if (gr < cnt) {
                k4 = *(const float4*)(g_k + base + (size_t)gr * DD + c);
                v4 = *(const float4*)(g_v + base + (size_t)gr * DD + c);
            }
            *(float4*)(Ks + r * LDP + c) = k4;
            *(float4*)(Vs + r * LDP + c) = v4;
        }
        if (tid < 64) mb[tid] = (kt + tid < cnt) ? 0.f : -1e30f;
        __syncthreads();

        // Phase A: S = Q @ K^T
        float s[4][4] = {};
        #pragma unroll
        for (int d4 = 0; d4 < 16; d4++) {
            float4 q4[4], k4[4];
            #pragma unroll
            for (int i = 0; i < 4; i++)
                q4[i] = *(const float4*)(Qs + (ty * 4 + i) * LDP + d4 * 4);
            #pragma unroll
            for (int j = 0; j < 4; j++)
                k4[j] = *(const float4*)(Ks + (tx + 16 * j) * LDP + d4 * 4);
            #pragma unroll
            for (int i = 0; i < 4; i++)
                #pragma unroll
                for (int j = 0; j < 4; j++)
                    s[i][j] += q4[i].x * k4[j].x + q4[i].y * k4[j].y
                             + q4[i].z * k4[j].z + q4[i].w * k4[j].w;
        }

        // Online softmax per row
        #pragma unroll
        for (int i = 0; i < 4; i++) {
            float mloc = -1e30f;
            #pragma unroll
            for (int j = 0; j < 4; j++) {
                s[i][j] = s[i][j] * scale + mb[tx + 16 * j];
                mloc = fmaxf(mloc, s[i][j]);
            }
            #pragma unroll
            for (int off = 1; off < 16; off <<= 1)
                mloc = fmaxf(mloc, __shfl_xor_sync(0xffffffffu, mloc, off));
            const float mnew  = fmaxf(m_i[i], mloc);
            const float alpha = __expf(m_i[i] - mnew);
            float lloc = 0.f;
            #pragma unroll
            for (int j = 0; j < 4; j++) {
                const float p = __expf(s[i][j] - mnew);
                s[i][j] = p;
                lloc += p;
            }
            #pragma unroll
            for (int off = 1; off < 16; off <<= 1)
                lloc += __shfl_xor_sync(0xffffffffu, lloc, off);
            l_i[i] = l_i[i] * alpha + lloc;
            m_i[i] = mnew;
            #pragma unroll
            for (int j = 0; j < 4; j++) {
                o[i][j] *= alpha;
                Ps[(ty * 4 + i) * LDP + tx + 16 * j] = s[i][j];
            }
        }
        __syncthreads();

        // Phase B: O += P @ V
        #pragma unroll 8
        for (int jj = 0; jj < 64; jj++) {
            float p_[4], v_[4];
            #pragma unroll
            for (int i = 0; i < 4; i++) p_[i] = Ps[(ty * 4 + i) * LDP + jj];
            #pragma unroll
            for (int j = 0; j < 4; j++) v_[j] = Vs[jj * LDP + tx + 16 * j];
            #pragma unroll
            for (int i = 0; i < 4; i++)
                #pragma unroll
                for (int j = 0; j < 4; j++)
                    o[i][j] += p_[i] * v_[j];
        }
    }

    #pragma unroll
    for (int i = 0; i < 4; i++) {
        const float inv = 1.0f / l_i[i];
        const int r = q0 + ty * 4 + i;
        #pragma unroll
        for (int j = 0; j < 4; j++) {
            const int d = tx + 16 * j;
            g_att[((size_t)(b * NN + r)) * CC + h * 64 + d] = o[i][j] * inv;
        }
    }
}

// ---------------------------------------------------------------------------

extern "C" void kernel_launch(void* const* d_in, const int* in_sizes, int n_in,
                              void* d_out, int out_size)
{
    const float* x      = (const float*)d_in[0];
    const float* mask   = (const float*)d_in[1];
    const float* qkv_w  = (const float*)d_in[2];
    const float* proj_w = (const float*)d_in[3];
    const float* proj_b = (const float*)d_in[4];
    float* out = (float*)d_out;

    const int smem_attn = (4 * 64 * LDP + 64) * (int)sizeof(float); // 69,888 B
    cudaFuncSetAttribute(attn_kernel,
                         cudaFuncAttributeMaxDynamicSharedMemorySize, smem_attn);

    // 1) Compact visible keys (exact: masked keys underflow to 0 in fp32)
    compact_kernel<<<BB, 1024>>>(mask);
    // 2) Q projection (all positions)
    gemm_k<0><<<dim3(CC / 64, (BB * NN) / 128), 256>>>(x, qkv_w, nullptr, nullptr);
    // 3) K/V projection (compacted positions only)
    gemm_k<1><<<dim3(2 * CC / 64, NN / 128, BB), 256>>>(x, qkv_w + 768 * CC,
                                                        nullptr, nullptr);
    // 4) Fused flash attention over compacted keys
    attn_kernel<<<dim3(NN / 64, HH, BB), 256, smem_attn>>>();
    // 5) Output projection + bias
    gemm_k<2><<<dim3(CC / 64, (BB * NN) / 128), 256>>>(nullptr, proj_w, proj_b, out);
}

// round 3
// speedup vs baseline: 2.9025x; 1.5127x over previous
#include <cuda_runtime.h>
#include <cstdint>

#define BB   2
#define HH   12
#define NN   2048
#define CC   768
#define DD   64
#define NT   (CC/8)

// Scratch (no allocations allowed)
__device__ float g_q[BB*HH*NN*DD];
__device__ float g_k[BB*HH*NN*DD];
__device__ float g_v[BB*HH*NN*DD];
__device__ float g_att[BB*NN*CC];
__device__ int   g_idx[BB*NN];
__device__ int   g_cnt[BB];

// ---------------------------------------------------------------------------
// Compaction: per batch, gather indices of visible keys (mask == 0).
// Masked keys get -1000 bias -> exp underflows to exactly 0 in fp32, so
// dropping them is EXACT vs the fp32 reference.
// ---------------------------------------------------------------------------
__global__ __launch_bounds__(1024) void compact_kernel(const float* __restrict__ mask)
{
    __shared__ int wsum[32];
    const int b = blockIdx.x;
    const int t = threadIdx.x;
    const int p0 = 2 * t, p1 = 2 * t + 1;
    const int v0 = (mask[b * NN + p0] == 0.0f) ? 1 : 0;
    const int v1 = (mask[b * NN + p1] == 0.0f) ? 1 : 0;
    const int s  = v0 + v1;

    int sc = s;
    #pragma unroll
    for (int o = 1; o < 32; o <<= 1) {
        int n = __shfl_up_sync(0xffffffffu, sc, o);
        if ((t & 31) >= o) sc += n;
    }
    if ((t & 31) == 31) wsum[t >> 5] = sc;
    __syncthreads();
    if (t < 32) {
        int w = wsum[t];
        #pragma unroll
        for (int o = 1; o < 32; o <<= 1) {
            int n = __shfl_up_sync(0xffffffffu, w, o);
            if (t >= o) w += n;
        }
        wsum[t] = w;
    }
    __syncthreads();
    const int excl = (sc - s) + ((t >= 32) ? wsum[(t >> 5) - 1] : 0);
    if (v0) g_idx[b * NN + excl] = p0;
    if (v1) g_idx[b * NN + excl + v0] = p1;
    if (t == 1023) g_cnt[b] = excl + s;
}

// ---------------------------------------------------------------------------
// 128x64 GEMM tile, K-step 8, double-buffered smem, 8x4 per thread. (fp32)
// ---------------------------------------------------------------------------
template<int MODE>
__global__ __launch_bounds__(256) void gemm_k(const float* __restrict__ A,
                                              const float* __restrict__ W,
                                              const float* __restrict__ bias,
                                              float* __restrict__ out)
{
    __shared__ __align__(16) float As[2][8][132];
    __shared__ __align__(16) float Bs[2][8][68];

    const int tid = threadIdx.x;
    const int n0 = blockIdx.x * 64;
    const int m0 = blockIdx.y * 128;
    int b = 0, cnt = 0;
    if (MODE == 1) {
        b = blockIdx.z;
        cnt = g_cnt[b];
        if (m0 >= cnt) return;
    }

    const float* Ap = (MODE == 2) ? g_att : A;

    const int lr = tid >> 1;
    const int lk = (tid & 1) * 4;
    size_t a_off;
    if (MODE == 1) {
        const int mrow = m0 + lr;
        const int src  = (mrow < cnt) ? g_idx[b * NN + mrow] : 0;
        a_off = ((size_t)(b * NN + src)) * CC + lk;
    } else {
        a_off = (size_t)(m0 + lr) * CC + lk;
    }
    size_t b_off = 0;
    if (tid < 128) b_off = (size_t)(n0 + (tid >> 1)) * CC + lk;

    const int w = tid >> 5, lane = tid & 31;
    const int wy = w >> 1, wx = w & 1;
    const int ly = lane >> 3, lx = lane & 7;
    const int row0 = wy * 32 + ly * 4;
    const int col0 = wx * 32 + lx * 4;

    float acc[8][4] = {};

    float4 af = *(const float4*)(Ap + a_off);
    float4 bf = make_float4(0.f, 0.f, 0.f, 0.f);
    if (tid < 128) bf = *(const float4*)(W + b_off);

    int buf = 0;
    for (int kt = 0; kt < NT; kt++) {
        As[buf][lk + 0][lr] = af.x;
        As[buf][lk + 1][lr] = af.y;
        As[buf][lk + 2][lr] = af.z;
        As[buf][lk + 3][lr] = af.w;
        if (tid < 128) {
            const int br = tid >> 1;
            Bs[buf][lk + 0][br] = bf.x;
            Bs[buf][lk + 1][br] = bf.y;
            Bs[buf][lk + 2][br] = bf.z;
            Bs[buf][lk + 3][br] = bf.w;
        }
        __syncthreads();
        if (kt + 1 < NT) {
            af = *(const float4*)(Ap + a_off + (kt + 1) * 8);
            if (tid < 128) bf = *(const float4*)(W + b_off + (kt + 1) * 8);
        }
        #pragma unroll
        for (int kc = 0; kc < 8; kc++) {
            float4 a0 = *(const float4*)&As[buf][kc][row0];
            float4 a1 = *(const float4*)&As[buf][kc][row0 + 16];
            float4 b4 = *(const float4*)&Bs[buf][kc][col0];
            const float av[8] = {a0.x, a0.y, a0.z, a0.w, a1.x, a1.y, a1.z, a1.w};
            const float bv[4] = {b4.x, b4.y, b4.z, b4.w};
            #pragma unroll
            for (int i = 0; i < 8; i++)
                #pragma unroll
                for (int j = 0; j < 4; j++)
                    acc[i][j] += av[i] * bv[j];
        }
        buf ^= 1;
    }

    #pragma unroll
    for (int i = 0; i < 8; i++) {
        const int rloc = row0 + ((i < 4) ? i : (i + 12));
        const int m = m0 + rloc;
        if (MODE == 1 && m >= cnt) continue;
        #pragma unroll
        for (int j = 0; j < 4; j++) {
            const int c = n0 + col0 + j;
            const float v = acc[i][j];
            if (MODE == 0) {
                const int bpos = m >> 11, nn = m & 2047;
                const int h = c >> 6, d = c & 63;
                g_q[(((size_t)bpos * HH + h) * NN + nn) * DD + d] = v;
            } else if (MODE == 1) {
                const bool isv = (c >= 768);
                const int cc2 = isv ? (c - 768) : c;
                const int h = cc2 >> 6, d = cc2 & 63;
                float* dst = isv ? g_v : g_k;
                dst[(((size_t)b * HH + h) * NN + m) * DD + d] = v;
            } else {
                out[(size_t)m * CC + c] = v + bias[c];
            }
        }
    }
}

// ---------------------------------------------------------------------------
// Flash attention with tf32 mma.sync (m16n8k8), compacted keys.
// 4 warps x 16 q-rows; K pitch 68, V pitch 72, per-warp P pitch 68
// (all fragment LDS patterns conflict-free).
// ---------------------------------------------------------------------------
#define KP 68
#define VP 72

__device__ __forceinline__ void mma_tf32(float* d, const uint32_t* a,
                                         uint32_t b0, uint32_t b1)
{
    asm volatile(
        "mma.sync.aligned.m16n8k8.row.col.f32.tf32.tf32.f32 "
        "{%0,%1,%2,%3},{%4,%5,%6,%7},{%8,%9},{%0,%1,%2,%3};"
        : "+f"(d[0]), "+f"(d[1]), "+f"(d[2]), "+f"(d[3])
        : "r"(a[0]), "r"(a[1]), "r"(a[2]), "r"(a[3]), "r"(b0), "r"(b1));
}

__device__ __forceinline__ uint32_t to_tf32(float f)
{
    uint32_t u;
    asm("cvt.rna.tf32.f32 %0, %1;" : "=r"(u) : "f"(f));
    return u;
}

__global__ __launch_bounds__(128) void attn_kernel()
{
    extern __shared__ float sm[];
    float* Ks = sm;                  // 64 * 68
    float* Vs = Ks + 64 * KP;        // 64 * 72
    float* Ps = Vs + 64 * VP;        // 64 * 68 (16 rows per warp)

    const int tid  = threadIdx.x;
    const int w    = tid >> 5, lane = tid & 31;
    const int lq   = lane >> 2;      // 0..7
    const int lr   = lane & 3;       // 0..3
    const int q0   = blockIdx.x * 64;
    const int h    = blockIdx.y;
    const int b    = blockIdx.z;
    const int cnt  = g_cnt[b];
    const size_t base = ((size_t)(b * HH + h)) * NN * DD;
    float* Pw = Ps + w * 16 * KP;

    // Stage Q through Ks (coalesced), then pull loop-invariant A-fragments,
    // pre-scaled by 1/sqrt(D) and rounded to tf32.
    for (int e = tid * 4; e < 64 * 64; e += 512) {
        const int r = e >> 6, c = e & 63;
        *(float4*)(Ks + r * KP + c) =
            *(const float4*)(g_q + base + (size_t)(q0 + r) * DD + c);
    }
    __syncthreads();
    uint32_t qa[8][4];
    #pragma unroll
    for (int kc = 0; kc < 8; kc++) {
        const int r0 = w * 16 + lq;
        qa[kc][0] = to_tf32(Ks[r0 * KP + kc * 8 + lr] * 0.125f);
        qa[kc][1] = to_tf32(Ks[(r0 + 8) * KP + kc * 8 + lr] * 0.125f);
        qa[kc][2] = to_tf32(Ks[r0 * KP + kc * 8 + lr + 4] * 0.125f);
        qa[kc][3] = to_tf32(Ks[(r0 + 8) * KP + kc * 8 + lr + 4] * 0.125f);
    }

    float o[8][4] = {};
    float m0 = -1e30f, m1 = -1e30f, l0 = 0.f, l1 = 0.f;
    const float4 z4 = make_float4(0.f, 0.f, 0.f, 0.f);

    for (int kt = 0; kt < cnt; kt += 64) {
        __syncthreads();
        for (int e = tid * 4; e < 64 * 64; e += 512) {
            const int r = e >> 6, c = e & 63;
            const int gr = kt + r;
            float4 k4 = z4, v4 = z4;
            if (gr < cnt) {
                k4 = *(const float4*)(g_k + base + (size_t)gr * DD + c);
                v4 = *(const float4*)(g_v + base + (size_t)gr * DD + c);
            }
            *(float4*)(Ks + r * KP + c) = k4;
            *(float4*)(Vs + r * VP + c) = v4;
        }
        __syncthreads();

        // S = Q @ K^T  (8 n-tiles of 8 keys)
        float s[8][4];
        #pragma unroll
        for (int nt = 0; nt < 8; nt++) {
            s[nt][0] = s[nt][1] = s[nt][2] = s[nt][3] = 0.f;
            #pragma unroll
            for (int kc = 0; kc < 8; kc++) {
                const uint32_t b0 =
                    __float_as_uint(Ks[(nt * 8 + lq) * KP + kc * 8 + lr]);
                const uint32_t b1 =
                    __float_as_uint(Ks[(nt * 8 + lq) * KP + kc * 8 + lr + 4]);
                mma_tf32(s[nt], qa[kc], b0, b1);
            }
        }

        // Online softmax (rows lq and lq+8; quad lanes share rows)
        float mx0 = -1e30f, mx1 = -1e30f;
        #pragma unroll
        for (int nt = 0; nt < 8; nt++) {
            const int col = kt + nt * 8 + 2 * lr;
            if (col >= cnt)     { s[nt][0] = -1e30f; s[nt][2] = -1e30f; }
            if (col + 1 >= cnt) { s[nt][1] = -1e30f; s[nt][3] = -1e30f; }
            mx0 = fmaxf(mx0, fmaxf(s[nt][0], s[nt][1]));
            mx1 = fmaxf(mx1, fmaxf(s[nt][2], s[nt][3]));
        }
        mx0 = fmaxf(mx0, __shfl_xor_sync(0xffffffffu, mx0, 1));
        mx0 = fmaxf(mx0, __shfl_xor_sync(0xffffffffu, mx0, 2));
        mx1 = fmaxf(mx1, __shfl_xor_sync(0xffffffffu, mx1, 1));
        mx1 = fmaxf(mx1, __shfl_xor_sync(0xffffffffu, mx1, 2));
        const float mn0 = fmaxf(m0, mx0), mn1 = fmaxf(m1, mx1);
        const float al0 = __expf(m0 - mn0), al1 = __expf(m1 - mn1);
        m0 = mn0; m1 = mn1;

        float ls0 = 0.f, ls1 = 0.f;
        #pragma unroll
        for (int nt = 0; nt < 8; nt++) {
            const float p0 = __expf(s[nt][0] - mn0);
            const float p1 = __expf(s[nt][1] - mn0);
            const float p2 = __expf(s[nt][2] - mn1);
            const float p3 = __expf(s[nt][3] - mn1);
            ls0 += p0 + p1; ls1 += p2 + p3;
            const int c0 = nt * 8 + 2 * lr;
            Pw[lq * KP + c0]           = __uint_as_float(to_tf32(p0));
            Pw[lq * KP + c0 + 1]       = __uint_as_float(to_tf32(p1));
            Pw[(lq + 8) * KP + c0]     = __uint_as_float(to_tf32(p2));
            Pw[(lq + 8) * KP + c0 + 1] = __uint_as_float(to_tf32(p3));
        }
        ls0 += __shfl_xor_sync(0xffffffffu, ls0, 1);
        ls0 += __shfl_xor_sync(0xffffffffu, ls0, 2);
        ls1 += __shfl_xor_sync(0xffffffffu, ls1, 1);
        ls1 += __shfl_xor_sync(0xffffffffu, ls1, 2);
        l0 = l0 * al0 + ls0;
        l1 = l1 * al1 + ls1;
        #pragma unroll
        for (int dt = 0; dt < 8; dt++) {
            o[dt][0] *= al0; o[dt][1] *= al0;
            o[dt][2] *= al1; o[dt][3] *= al1;
        }
        __syncwarp();

        // O += P @ V
        #pragma unroll
        for (int kc = 0; kc < 8; kc++) {
            uint32_t pa[4];
            pa[0] = __float_as_uint(Pw[lq * KP + kc * 8 + lr]);
            pa[1] = __float_as_uint(Pw[(lq + 8) * KP + kc * 8 + lr]);
            pa[2] = __float_as_uint(Pw[lq * KP + kc * 8 + lr + 4]);
            pa[3] = __float_as_uint(Pw[(lq + 8) * KP + kc * 8 + lr + 4]);
            #pragma unroll
            for (int dt = 0; dt < 8; dt++) {
                const uint32_t b0 =
                    __float_as_uint(Vs[(kc * 8 + lr) * VP + dt * 8 + lq]);
                const uint32_t b1 =
                    __float_as_uint(Vs[(kc * 8 + lr + 4) * VP + dt * 8 + lq]);
                mma_tf32(o[dt], pa, b0, b1);
            }
        }
        __syncwarp();
    }

    // Epilogue: normalize and write [B,N,C] (c = h*64 + d)
    const float inv0 = 1.0f / l0, inv1 = 1.0f / l1;
    const int r0 = q0 + w * 16 + lq, r1 = r0 + 8;
    #pragma unroll
    for (int dt = 0; dt < 8; dt++) {
        const int d = h * 64 + dt * 8 + 2 * lr;
        *(float2*)(g_att + ((size_t)(b * NN + r0)) * CC + d) =
            make_float2(o[dt][0] * inv0, o[dt][1] * inv0);
        *(float2*)(g_att + ((size_t)(b * NN + r1)) * CC + d) =
            make_float2(o[dt][2] * inv1, o[dt][3] * inv1);
    }
}

// ---------------------------------------------------------------------------

extern "C" void kernel_launch(void* const* d_in, const int* in_sizes, int n_in,
                              void* d_out, int out_size)
{
    const float* x      = (const float*)d_in[0];
    const float* mask   = (const float*)d_in[1];
    const float* qkv_w  = (const float*)d_in[2];
    const float* proj_w = (const float*)d_in[3];
    const float* proj_b = (const float*)d_in[4];
    float* out = (float*)d_out;

    const int smem_attn = (64 * KP + 64 * VP + 64 * KP) * (int)sizeof(float); // 53,248 B
    cudaFuncSetAttribute(attn_kernel,
                         cudaFuncAttributeMaxDynamicSharedMemorySize, smem_attn);

    compact_kernel<<<BB, 1024>>>(mask);
    gemm_k<0><<<dim3(CC / 64, (BB * NN) / 128), 256>>>(x, qkv_w, nullptr, nullptr);
    gemm_k<1><<<dim3(2 * CC / 64, NN / 128, BB), 256>>>(x, qkv_w + 768 * CC,
                                                        nullptr, nullptr);
    attn_kernel<<<dim3(NN / 64, HH, BB), 128, smem_attn>>>();
    gemm_k<2><<<dim3(CC / 64, (BB * NN) / 128), 256>>>(nullptr, proj_w, proj_b, out);
}